// round 2
// baseline (speedup 1.0000x reference)
#include <cuda_runtime.h>
#include <cuda_bf16.h>

// Problem constants
#define B     8
#define CIN   64
#define CH    64
#define HH    128
#define WW    128
#define CS    128      // CIN + CH
#define COUT  256      // 4 * CH
#define HW    (HH * WW)
#define CKC   8        // input-channel chunk staged in smem
#define OCB   8        // output channels per block

// Scratch for conv output (gates), 8*256*128*128 floats = 134 MB.
// __device__ global (no allocation in kernel_launch).
__device__ float g_gates[(size_t)B * COUT * HW];

// ---------------------------------------------------------------------------
// Kernel 1: direct 3x3 conv of concat(x, prev_h) -> g_gates (+bias)
// Block: 256 threads, pixel tile 32x32 (thread = 2x2 px), 8 out-channels.
// Packed fp32x2 FMA: 2 x-adjacent pixels per 64-bit accumulator.
// ---------------------------------------------------------------------------
__global__ __launch_bounds__(256, 2)
void conv_gates_kernel(const float* __restrict__ x,
                       const float* __restrict__ ph,
                       const float* __restrict__ Wg,
                       const float* __restrict__ bg)
{
    __shared__ float  s_in[CKC][34][34];   // 36992 B
    __shared__ float2 s_w[OCB][CKC][9];    //  4608 B (weights pre-duplicated)

    const int tid = threadIdx.x;
    const int bx = blockIdx.x, by = blockIdx.y, bz = blockIdx.z;
    const int b   = bz >> 5;           // batch
    const int oc0 = (bz & 31) * OCB;   // first of 8 output channels
    const int qx = tid & 15, qy = tid >> 4;
    const int lx0 = qx * 2, ly0 = qy * 2;      // local 2x2 pixel origin
    const int gx0 = bx * 32 + lx0;
    const int gy0 = by * 32 + ly0;

    unsigned long long acc[OCB][2];    // [oc][row], each holds 2 x-adjacent px
    #pragma unroll
    for (int oc = 0; oc < OCB; ++oc) { acc[oc][0] = 0ULL; acc[oc][1] = 0ULL; }

    const float* in0 = x  + (size_t)b * CIN * HW;
    const float* in1 = ph + (size_t)b * CH  * HW;

    for (int cc = 0; cc < CS / CKC; ++cc) {
        // ---- stage input tile (34x34 halo) for CKC channels ----
        for (int idx = tid; idx < CKC * 34 * 34; idx += 256) {
            int ci  = idx / (34 * 34);
            int rem = idx - ci * (34 * 34);
            int r = rem / 34;
            int c = rem - r * 34;
            int gy = by * 32 + r - 1;
            int gx = bx * 32 + c - 1;
            int cs = cc * CKC + ci;
            float v = 0.f;
            if ((unsigned)gy < (unsigned)HH && (unsigned)gx < (unsigned)WW) {
                v = (cs < CIN) ? in0[cs * HW + gy * WW + gx]
                               : in1[(cs - CIN) * HW + gy * WW + gx];
            }
            s_in[ci][r][c] = v;
        }
        // ---- stage weights, duplicated into both float2 lanes ----
        for (int idx = tid; idx < OCB * CKC * 9; idx += 256) {
            int oc  = idx / (CKC * 9);
            int rem = idx - oc * (CKC * 9);
            int ci = rem / 9;
            int t  = rem - ci * 9;
            float w = Wg[((size_t)(oc0 + oc) * CS + (cc * CKC + ci)) * 9 + t];
            s_w[oc][ci][t] = make_float2(w, w);
        }
        __syncthreads();

        #pragma unroll
        for (int ci = 0; ci < CKC; ++ci) {
            // 4x4 input patch covering the 2x2 output quad's 3x3 taps
            float p[4][4];
            #pragma unroll
            for (int i = 0; i < 4; ++i)
                #pragma unroll
                for (int j = 0; j < 4; ++j)
                    p[i][j] = s_in[ci][ly0 + i][lx0 + j];

            // pack shifted pairs: pr[row][kx] = (p[row][kx], p[row][kx+1])
            unsigned long long pr[4][3];
            #pragma unroll
            for (int i = 0; i < 4; ++i)
                #pragma unroll
                for (int kx = 0; kx < 3; ++kx)
                    asm("mov.b64 %0, {%1, %2};"
                        : "=l"(pr[i][kx]) : "f"(p[i][kx]), "f"(p[i][kx + 1]));

            #pragma unroll
            for (int oc = 0; oc < OCB; ++oc) {
                const unsigned long long* wp =
                    reinterpret_cast<const unsigned long long*>(&s_w[oc][ci][0]);
                #pragma unroll
                for (int ky = 0; ky < 3; ++ky) {
                    #pragma unroll
                    for (int kx = 0; kx < 3; ++kx) {
                        unsigned long long wv = wp[ky * 3 + kx];
                        asm("fma.rn.f32x2 %0, %1, %2, %0;"
                            : "+l"(acc[oc][0]) : "l"(pr[ky][kx]),     "l"(wv));
                        asm("fma.rn.f32x2 %0, %1, %2, %0;"
                            : "+l"(acc[oc][1]) : "l"(pr[ky + 1][kx]), "l"(wv));
                    }
                }
            }
        }
        __syncthreads();
    }

    // ---- epilogue: +bias, store float2 per row per oc ----
    #pragma unroll
    for (int oc = 0; oc < OCB; ++oc) {
        int ocg = oc0 + oc;
        float bias = __ldg(&bg[ocg]);
        float* gp = g_gates + ((size_t)b * COUT + ocg) * HW;
        #pragma unroll
        for (int r = 0; r < 2; ++r) {
            float lo, hi;
            asm("mov.b64 {%0, %1}, %2;" : "=f"(lo), "=f"(hi) : "l"(acc[oc][r]));
            *reinterpret_cast<float2*>(&gp[(gy0 + r) * WW + gx0]) =
                make_float2(lo + bias, hi + bias);
        }
    }
}

// ---------------------------------------------------------------------------
// Kernel 2: elementwise LSTM gating (memory-bound, float4 vectorized)
// ---------------------------------------------------------------------------
__device__ __forceinline__ float sigm_f(float v) {
    return 1.f / (1.f + __expf(-v));
}
__device__ __forceinline__ float tanh_f(float v) {
    return 2.f / (1.f + __expf(-2.f * v)) - 1.f;
}

__global__ __launch_bounds__(256)
void gate_kernel(const float* __restrict__ prev_c, float* __restrict__ out)
{
    const int N = B * CH * HW;                  // 8,388,608
    int i4 = blockIdx.x * blockDim.x + threadIdx.x;
    int base = i4 * 4;
    if (base >= N) return;

    int b = base / (CH * HW);
    int r = base - b * (CH * HW);
    size_t gb = (size_t)b * COUT * HW;

    float4 gi = *reinterpret_cast<const float4*>(g_gates + gb + 0 * CH * HW + r);
    float4 gf = *reinterpret_cast<const float4*>(g_gates + gb + 1 * CH * HW + r);
    float4 go = *reinterpret_cast<const float4*>(g_gates + gb + 2 * CH * HW + r);
    float4 gg = *reinterpret_cast<const float4*>(g_gates + gb + 3 * CH * HW + r);
    float4 pc = *reinterpret_cast<const float4*>(prev_c + base);

    float4 cell, hid;
    {
        float c0 = sigm_f(gi.x) * tanh_f(gg.x) + sigm_f(gf.x) * pc.x;
        cell.x = c0; hid.x = sigm_f(go.x) * tanh_f(c0);
        float c1 = sigm_f(gi.y) * tanh_f(gg.y) + sigm_f(gf.y) * pc.y;
        cell.y = c1; hid.y = sigm_f(go.y) * tanh_f(c1);
        float c2 = sigm_f(gi.z) * tanh_f(gg.z) + sigm_f(gf.z) * pc.z;
        cell.z = c2; hid.z = sigm_f(go.z) * tanh_f(c2);
        float c3 = sigm_f(gi.w) * tanh_f(gg.w) + sigm_f(gf.w) * pc.w;
        cell.w = c3; hid.w = sigm_f(go.w) * tanh_f(c3);
    }

    *reinterpret_cast<float4*>(out + base)     = hid;   // hidden
    *reinterpret_cast<float4*>(out + N + base) = cell;  // cell
}

// ---------------------------------------------------------------------------
extern "C" void kernel_launch(void* const* d_in, const int* in_sizes, int n_in,
                              void* d_out, int out_size)
{
    const float* x      = (const float*)d_in[0];
    const float* prev_h = (const float*)d_in[1];
    const float* prev_c = (const float*)d_in[2];
    const float* Wg     = (const float*)d_in[3];
    const float* bg     = (const float*)d_in[4];
    float* out = (float*)d_out;

    dim3 g1(WW / 32, HH / 32, B * (COUT / OCB));   // (4, 4, 256)
    conv_gates_kernel<<<g1, 256>>>(x, prev_h, Wg, bg);

    int n4 = (B * CH * HW) / 4;                    // 2,097,152
    gate_kernel<<<n4 / 256, 256>>>(prev_c, out);
}

// round 6
// speedup vs baseline: 5.4362x; 5.4362x over previous
#include <cuda_runtime.h>
#include <cuda_bf16.h>
#include <cstdint>

// ---------------------------------------------------------------------------
// Problem constants
// ---------------------------------------------------------------------------
#define B     8
#define CIN   64
#define CH    64
#define HH    128
#define WW    128
#define CS    128              // CIN + CH
#define COUT  256              // 4 * CH
#define HW    (HH * WW)
#define KTOT  1152             // CS * 9
#define NCHUNK 18              // 9 taps x 2 channel-halves (K=64 each)
#define NTOT  (B * CH * HW)    // elements per output tensor

// SMEM staging (padded pitch 144B = 72 bf16 -> conflict-free ldmatrix)
#define APITCH 144
#define A_HALF 18432           // 128 rows * 144B
#define B_HALF 36864           // 256 rows * 144B
#define OFF_AH 0
#define OFF_AL A_HALF          // 18432
#define OFF_BH (2 * A_HALF)    // 36864
#define OFF_BL (2 * A_HALF + B_HALF)  // 73728
#define STAGE  (2 * A_HALF + 2 * B_HALF)  // 110592
#define SMEM_TOTAL (2 * STAGE) // 221184

#define GPITCH 258             // fp32 gate staging pitch (floats)

// ---------------------------------------------------------------------------
// Device scratch (no allocations allowed in kernel_launch)
// ---------------------------------------------------------------------------
__device__ __nv_bfloat16 g_inT_hi[(size_t)B * HH * WW * CS];  // [b][y][x][ci]
__device__ __nv_bfloat16 g_inT_lo[(size_t)B * HH * WW * CS];
__device__ __nv_bfloat16 g_w_hi[(size_t)COUT * KTOT];         // [n][k=tap*128+ci]
__device__ __nv_bfloat16 g_w_lo[(size_t)COUT * KTOT];

// ---------------------------------------------------------------------------
// Helpers (base ISA only: ldmatrix / mma.sync / cp.async)
// ---------------------------------------------------------------------------
__device__ __forceinline__ uint32_t smem_to_u32(const void* p) {
    uint32_t a;
    asm("{ .reg .u64 t; cvta.to.shared.u64 t, %1; cvt.u32.u64 %0, t; }"
        : "=r"(a) : "l"(p));
    return a;
}

__device__ __forceinline__ void cp16(uint32_t dst, const void* src, bool valid) {
    int sz = valid ? 16 : 0;
    asm volatile("cp.async.cg.shared.global [%0], [%1], 16, %2;"
                 :: "r"(dst), "l"(src), "r"(sz) : "memory");
}

#define LDSM_X4(r, addr) \
    asm volatile("ldmatrix.sync.aligned.m8n8.x4.shared.b16 {%0,%1,%2,%3}, [%4];" \
        : "=r"((r)[0]), "=r"((r)[1]), "=r"((r)[2]), "=r"((r)[3]) : "r"(addr))

__device__ __forceinline__ void mma_bf16(float* d, const uint32_t* a,
                                         uint32_t b0, uint32_t b1) {
    asm volatile(
        "mma.sync.aligned.m16n8k16.row.col.f32.bf16.bf16.f32 "
        "{%0,%1,%2,%3}, {%4,%5,%6,%7}, {%8,%9}, {%0,%1,%2,%3};"
        : "+f"(d[0]), "+f"(d[1]), "+f"(d[2]), "+f"(d[3])
        : "r"(a[0]), "r"(a[1]), "r"(a[2]), "r"(a[3]), "r"(b0), "r"(b1));
}

__device__ __forceinline__ float sigm_f(float v) { return 1.f / (1.f + __expf(-v)); }
__device__ __forceinline__ float tanh_f(float v) { return 2.f / (1.f + __expf(-2.f * v)) - 1.f; }

// ---------------------------------------------------------------------------
// Prep 1: transpose + hi/lo split of concat(x, prev_h) -> [b][y][x][ci] bf16
// ---------------------------------------------------------------------------
__global__ __launch_bounds__(256)
void prep_input_kernel(const float* __restrict__ x, const float* __restrict__ ph)
{
    __shared__ float s[64][129];
    const int bid = blockIdx.x;
    const int b = bid >> 7, y = bid & 127;
    const int tid = threadIdx.x;

    #pragma unroll
    for (int h2 = 0; h2 < 2; ++h2) {
        const int cbase = h2 * 64;
        for (int idx = tid; idx < 64 * 128; idx += 256) {
            int ci = idx >> 7, xx = idx & 127;
            int cs = cbase + ci;
            const float* src = (cs < CIN)
                ? (x  + ((size_t)b * CIN + cs) * HW)
                : (ph + ((size_t)b * CH + (cs - CIN)) * HW);
            s[ci][xx] = src[y * WW + xx];
        }
        __syncthreads();
        for (int idx = tid; idx < 128 * 64; idx += 256) {
            int xx = idx >> 6, ci = idx & 63;
            float v = s[ci][xx];
            __nv_bfloat16 hi = __float2bfloat16(v);
            __nv_bfloat16 lo = __float2bfloat16(v - __bfloat162float(hi));
            size_t o = ((size_t)(b * HH + y) * WW + xx) * CS + cbase + ci;
            g_inT_hi[o] = hi;
            g_inT_lo[o] = lo;
        }
        __syncthreads();
    }
}

// ---------------------------------------------------------------------------
// Prep 2: weights [oc][cs][ky][kx] -> [n][k = tap*128 + cs], hi/lo bf16
// ---------------------------------------------------------------------------
__global__ __launch_bounds__(256)
void prep_w_kernel(const float* __restrict__ Wg)
{
    int idx = blockIdx.x * blockDim.x + threadIdx.x;
    if (idx >= COUT * KTOT) return;
    int n = idx / KTOT, k = idx - n * KTOT;
    int tap = k >> 7, cs = k & 127;
    float v = Wg[(size_t)n * KTOT + cs * 9 + tap];
    __nv_bfloat16 hi = __float2bfloat16(v);
    g_w_hi[idx] = hi;
    g_w_lo[idx] = __float2bfloat16(v - __bfloat162float(hi));
}

// ---------------------------------------------------------------------------
// Main: implicit-GEMM conv (mma.sync bf16 3-pass split) + fused LSTM gating.
// One CTA = one image row: M=128 px, N=256 gates, K=1152 (18 chunks of 64).
// 512 threads = 16 warps in 4(M) x 4(N) grid; warp tile 32x64.
// ---------------------------------------------------------------------------
__device__ __forceinline__ void issue_chunk(int chunk, uint32_t base,
                                            int b, int y, int tid)
{
    const int tap = chunk >> 1;
    const int ci0 = (chunk & 1) * 64;
    const int dy = tap / 3 - 1, dxx = tap % 3 - 1;
    const int yy = y + dy;
    const bool yok = (unsigned)yy < (unsigned)HH;
    const int yc = yok ? yy : 0;

    // A: 128 rows x 8 segs x {hi,lo} = 2048 cp.async -> 4 per thread
    #pragma unroll
    for (int q = 0; q < 4; ++q) {
        int idx = q * 512 + tid;
        int arr = idx >> 10;
        int rem = idx & 1023;
        int row = rem >> 3, seg = rem & 7;
        int xr = row + dxx;
        bool valid = yok && ((unsigned)xr < (unsigned)WW);
        int xc = ((unsigned)xr < (unsigned)WW) ? xr : 0;
        const __nv_bfloat16* g = arr ? g_inT_lo : g_inT_hi;
        const void* src = g + (((size_t)(b * HH + yc) * WW + xc) * CS + ci0 + seg * 8);
        uint32_t dst = base + arr * A_HALF + row * APITCH + seg * 16;
        cp16(dst, src, valid);
    }
    // B: 256 rows x 8 segs x {hi,lo} = 4096 -> 8 per thread
    #pragma unroll
    for (int q = 0; q < 8; ++q) {
        int idx = q * 512 + tid;
        int arr = idx >> 11;
        int rem = idx & 2047;
        int n = rem >> 3, seg = rem & 7;
        const __nv_bfloat16* g = arr ? g_w_lo : g_w_hi;
        const void* src = g + ((size_t)n * KTOT + tap * 128 + ci0 + seg * 8);
        uint32_t dst = base + OFF_BH + arr * B_HALF + n * APITCH + seg * 16;
        cp16(dst, src, true);
    }
}

__global__ __launch_bounds__(512)
void convlstm_mma_kernel(const float* __restrict__ prev_c,
                         const float* __restrict__ bg,
                         float* __restrict__ out)
{
    extern __shared__ char smem[];
    const uint32_t sb = smem_to_u32(smem);
    const int tid = threadIdx.x, wid = tid >> 5, lane = tid & 31;
    const int bid = blockIdx.x;
    const int b = bid >> 7, y = bid & 127;
    const int m0 = (wid & 3) * 32;        // warp m origin
    const int n0w = (wid >> 2) * 64;      // warp n origin

    float acc[2][8][4];
    #pragma unroll
    for (int i = 0; i < 2; ++i)
        #pragma unroll
        for (int j = 0; j < 8; ++j)
            #pragma unroll
            for (int t = 0; t < 4; ++t) acc[i][j][t] = 0.f;

    issue_chunk(0, sb, b, y, tid);
    asm volatile("cp.async.commit_group;" ::: "memory");

    for (int c = 0; c < NCHUNK; ++c) {
        if (c + 1 < NCHUNK)
            issue_chunk(c + 1, sb + ((c + 1) & 1) * STAGE, b, y, tid);
        asm volatile("cp.async.commit_group;" ::: "memory");
        asm volatile("cp.async.wait_group 1;" ::: "memory");
        __syncthreads();

        const uint32_t base = sb + (c & 1) * STAGE;
        const uint32_t Ah = base + OFF_AH, Al = base + OFF_AL;
        const uint32_t Bh = base + OFF_BH, Bl = base + OFF_BL;

        #pragma unroll
        for (int s = 0; s < 4; ++s) {           // 4 x k16 steps per chunk
            uint32_t ah[2][4], al[2][4];
            #pragma unroll
            for (int i = 0; i < 2; ++i) {
                uint32_t r = m0 + i * 16 + (lane & 15);
                uint32_t off = r * APITCH + s * 32 + (lane >> 4) * 16;
                LDSM_X4(ah[i], Ah + off);
                LDSM_X4(al[i], Al + off);
            }
            #pragma unroll
            for (int nh = 0; nh < 2; ++nh) {    // two n32 halves
                uint32_t bh[2][4], bl[2][4];
                #pragma unroll
                for (int j2 = 0; j2 < 2; ++j2) {
                    uint32_t n = n0w + nh * 32 + j2 * 16
                               + ((lane >> 4) << 3) + (lane & 7);
                    uint32_t off = n * APITCH + s * 32 + ((lane >> 3) & 1) * 16;
                    LDSM_X4(bh[j2], Bh + off);
                    LDSM_X4(bl[j2], Bl + off);
                }
                #pragma unroll
                for (int i = 0; i < 2; ++i)
                    #pragma unroll
                    for (int j = 0; j < 4; ++j) {  // 4 n8 tiles in this n32
                        float* d = acc[i][nh * 4 + j];
                        uint32_t b0h = bh[j >> 1][(j & 1) * 2];
                        uint32_t b1h = bh[j >> 1][(j & 1) * 2 + 1];
                        uint32_t b0l = bl[j >> 1][(j & 1) * 2];
                        uint32_t b1l = bl[j >> 1][(j & 1) * 2 + 1];
                        mma_bf16(d, ah[i], b0h, b1h);   // hi*hi
                        mma_bf16(d, ah[i], b0l, b1l);   // hi*lo
                        mma_bf16(d, al[i], b0h, b1h);   // lo*hi
                    }
            }
        }
        __syncthreads();
    }

    // ---- epilogue: acc -> smem gate staging [px][n] fp32 ----
    float* sg = (float*)smem;
    #pragma unroll
    for (int i = 0; i < 2; ++i)
        #pragma unroll
        for (int j = 0; j < 8; ++j) {
            int row = m0 + i * 16 + (lane >> 2);
            int col = n0w + j * 8 + (lane & 3) * 2;
            *(float2*)&sg[row * GPITCH + col] =
                make_float2(acc[i][j][0], acc[i][j][1]);
            *(float2*)&sg[(row + 8) * GPITCH + col] =
                make_float2(acc[i][j][2], acc[i][j][3]);
        }
    __syncthreads();

    // ---- fused LSTM gating, coalesced writes over px ----
    const int px = tid & 127;
    #pragma unroll
    for (int t = 0; t < 16; ++t) {
        int c = t * 4 + (tid >> 7);           // 0..63
        float gi = sg[px * GPITCH + c]        + __ldg(&bg[c]);
        float gf = sg[px * GPITCH + 64 + c]   + __ldg(&bg[64 + c]);
        float go = sg[px * GPITCH + 128 + c]  + __ldg(&bg[128 + c]);
        float gg = sg[px * GPITCH + 192 + c]  + __ldg(&bg[192 + c]);
        float ig = sigm_f(gi), fg = sigm_f(gf), og = sigm_f(go), cg = tanh_f(gg);
        size_t idx = ((size_t)(b * CH + c)) * HW + y * WW + px;
        float pc = prev_c[idx];
        float cell = ig * cg + fg * pc;
        float hid  = og * tanh_f(cell);
        out[idx] = hid;
        out[(size_t)NTOT + idx] = cell;
    }
}

// ---------------------------------------------------------------------------
extern "C" void kernel_launch(void* const* d_in, const int* in_sizes, int n_in,
                              void* d_out, int out_size)
{
    const float* x      = (const float*)d_in[0];
    const float* prev_h = (const float*)d_in[1];
    const float* prev_c = (const float*)d_in[2];
    const float* Wg     = (const float*)d_in[3];
    const float* bg     = (const float*)d_in[4];
    float* out = (float*)d_out;

    static bool attr_done = false;
    if (!attr_done) {
        cudaFuncSetAttribute(convlstm_mma_kernel,
                             cudaFuncAttributeMaxDynamicSharedMemorySize, SMEM_TOTAL);
        attr_done = true;
    }

    prep_input_kernel<<<B * HH, 256>>>(x, prev_h);
    prep_w_kernel<<<(COUT * KTOT + 255) / 256, 256>>>(Wg);
    convlstm_mma_kernel<<<B * HH, 512, SMEM_TOTAL>>>(prev_c, bg, out);
}

// round 8
// speedup vs baseline: 6.4534x; 1.1871x over previous
#include <cuda_runtime.h>
#include <cuda_fp16.h>
#include <cstdint>

// ---------------------------------------------------------------------------
// Problem constants
// ---------------------------------------------------------------------------
#define B     8
#define CIN   64
#define CH    64
#define HH    128
#define WW    128
#define CS    128              // CIN + CH
#define COUT  256              // 4 * CH
#define HW    (HH * WW)
#define KTOT  1152             // CS * 9
#define NCHUNK 18              // 9 taps x 2 channel-halves (K=64 each)
#define NTOT  (B * CH * HW)

// SMEM staging (padded pitch 144B = 72 fp16 -> conflict-free ldmatrix)
#define APITCH 144
#define A_HALF 18432           // 128 rows * 144B
#define B_TILE 36864           // 256 rows * 144B
#define OFF_AH 0
#define OFF_AL A_HALF          // 18432
#define OFF_B  (2 * A_HALF)    // 36864
#define STAGE  (2 * A_HALF + B_TILE)   // 73728
#define SMEM_TOTAL (2 * STAGE)         // 147456

#define GPITCH 257             // fp32 gate staging pitch (floats, odd->no conflicts)

// ---------------------------------------------------------------------------
// Device scratch
// ---------------------------------------------------------------------------
__device__ __half g_inT_hi[(size_t)B * HH * WW * CS];  // [b][y][x][ci]
__device__ __half g_inT_lo[(size_t)B * HH * WW * CS];
__device__ __half g_w[(size_t)COUT * KTOT];            // [n][k=tap*128+ci]

// ---------------------------------------------------------------------------
// Helpers (base ISA only)
// ---------------------------------------------------------------------------
__device__ __forceinline__ uint32_t smem_to_u32(const void* p) {
    uint32_t a;
    asm("{ .reg .u64 t; cvta.to.shared.u64 t, %1; cvt.u32.u64 %0, t; }"
        : "=r"(a) : "l"(p));
    return a;
}

__device__ __forceinline__ void cp16(uint32_t dst, const void* src, bool valid) {
    int sz = valid ? 16 : 0;
    asm volatile("cp.async.cg.shared.global [%0], [%1], 16, %2;"
                 :: "r"(dst), "l"(src), "r"(sz) : "memory");
}

#define LDSM_X4(r, addr) \
    asm volatile("ldmatrix.sync.aligned.m8n8.x4.shared.b16 {%0,%1,%2,%3}, [%4];" \
        : "=r"((r)[0]), "=r"((r)[1]), "=r"((r)[2]), "=r"((r)[3]) : "r"(addr))

__device__ __forceinline__ void mma_fp16(float* d, const uint32_t* a,
                                         uint32_t b0, uint32_t b1) {
    asm volatile(
        "mma.sync.aligned.m16n8k16.row.col.f32.f16.f16.f32 "
        "{%0,%1,%2,%3}, {%4,%5,%6,%7}, {%8,%9}, {%0,%1,%2,%3};"
        : "+f"(d[0]), "+f"(d[1]), "+f"(d[2]), "+f"(d[3])
        : "r"(a[0]), "r"(a[1]), "r"(a[2]), "r"(a[3]), "r"(b0), "r"(b1));
}

__device__ __forceinline__ float sigm_f(float v) { return 1.f / (1.f + __expf(-v)); }
__device__ __forceinline__ float tanh_f(float v) { return 2.f / (1.f + __expf(-2.f * v)) - 1.f; }

// ---------------------------------------------------------------------------
// Prep 1: transpose + fp16 hi/lo split of concat(x, prev_h) -> [b][y][x][ci]
// ---------------------------------------------------------------------------
__global__ __launch_bounds__(256)
void prep_input_kernel(const float* __restrict__ x, const float* __restrict__ ph)
{
    __shared__ float s[64][129];
    const int bid = blockIdx.x;
    const int b = bid >> 7, y = bid & 127;
    const int tid = threadIdx.x;

    #pragma unroll
    for (int h2 = 0; h2 < 2; ++h2) {
        const int cbase = h2 * 64;
        for (int idx = tid; idx < 64 * 128; idx += 256) {
            int ci = idx >> 7, xx = idx & 127;
            int cs = cbase + ci;
            const float* src = (cs < CIN)
                ? (x  + ((size_t)b * CIN + cs) * HW)
                : (ph + ((size_t)b * CH + (cs - CIN)) * HW);
            s[ci][xx] = src[y * WW + xx];
        }
        __syncthreads();
        for (int idx = tid; idx < 128 * 64; idx += 256) {
            int xx = idx >> 6, ci = idx & 63;
            float v = s[ci][xx];
            __half hi = __float2half_rn(v);
            __half lo = __float2half_rn(v - __half2float(hi));
            size_t o = ((size_t)(b * HH + y) * WW + xx) * CS + cbase + ci;
            g_inT_hi[o] = hi;
            g_inT_lo[o] = lo;
        }
        __syncthreads();
    }
}

// ---------------------------------------------------------------------------
// Prep 2: weights [oc][cs][ky][kx] -> [n][k = tap*128 + cs], fp16
// ---------------------------------------------------------------------------
__global__ __launch_bounds__(256)
void prep_w_kernel(const float* __restrict__ Wg)
{
    int idx = blockIdx.x * blockDim.x + threadIdx.x;
    if (idx >= COUT * KTOT) return;
    int n = idx / KTOT, k = idx - n * KTOT;
    int tap = k >> 7, cs = k & 127;
    g_w[idx] = __float2half_rn(Wg[(size_t)n * KTOT + cs * 9 + tap]);
}

// ---------------------------------------------------------------------------
// Main: implicit-GEMM conv (fp16 2-pass split) + fused LSTM gating.
// One CTA = one image row: M=128, N=256, K=1152 (18 chunks of 64).
// 256 threads = 8 warps in 2(M) x 4(N) grid; warp tile 64x64.
// ---------------------------------------------------------------------------
__device__ __forceinline__ void issue_chunk(int chunk, uint32_t base,
                                            int b, int y, int tid)
{
    const int tap = chunk >> 1;
    const int ci0 = (chunk & 1) * 64;
    const int dy = tap / 3 - 1, dxx = tap % 3 - 1;
    const int yy = y + dy;
    const bool yok = (unsigned)yy < (unsigned)HH;
    const int yc = yok ? yy : 0;

    // A: 2 arrays (hi/lo) x 128 rows x 8 segs = 2048 cp.async -> 8/thread
    #pragma unroll
    for (int q = 0; q < 8; ++q) {
        int idx = q * 256 + tid;
        int arr = idx >> 10;
        int rem = idx & 1023;
        int row = rem >> 3, seg = rem & 7;
        int xr = row + dxx;
        bool valid = yok && ((unsigned)xr < (unsigned)WW);
        int xc = ((unsigned)xr < (unsigned)WW) ? xr : 0;
        const __half* g = arr ? g_inT_lo : g_inT_hi;
        const void* src = g + (((size_t)(b * HH + yc) * WW + xc) * CS + ci0 + seg * 8);
        uint32_t dst = base + arr * A_HALF + row * APITCH + seg * 16;
        cp16(dst, src, valid);
    }
    // B: 256 rows x 8 segs = 2048 -> 8/thread
    #pragma unroll
    for (int q = 0; q < 8; ++q) {
        int idx = q * 256 + tid;
        int n = idx >> 3, seg = idx & 7;
        const void* src = g_w + ((size_t)n * KTOT + tap * 128 + ci0 + seg * 8);
        uint32_t dst = base + OFF_B + n * APITCH + seg * 16;
        cp16(dst, src, true);
    }
}

__global__ __launch_bounds__(256)
void convlstm_mma_kernel(const float* __restrict__ prev_c,
                         const float* __restrict__ bg,
                         float* __restrict__ out)
{
    extern __shared__ char smem[];
    const uint32_t sb = smem_to_u32(smem);
    const int tid = threadIdx.x, wid = tid >> 5, lane = tid & 31;
    const int bid = blockIdx.x;
    const int b = bid >> 7, y = bid & 127;
    const int m0 = (wid & 1) * 64;        // warp m origin (2 m-warps)
    const int n0w = (wid >> 1) * 64;      // warp n origin (4 n-warps)

    float acc[4][8][4];
    #pragma unroll
    for (int i = 0; i < 4; ++i)
        #pragma unroll
        for (int j = 0; j < 8; ++j)
            #pragma unroll
            for (int t = 0; t < 4; ++t) acc[i][j][t] = 0.f;

    issue_chunk(0, sb, b, y, tid);
    asm volatile("cp.async.commit_group;" ::: "memory");

    for (int c = 0; c < NCHUNK; ++c) {
        if (c + 1 < NCHUNK)
            issue_chunk(c + 1, sb + ((c + 1) & 1) * STAGE, b, y, tid);
        asm volatile("cp.async.commit_group;" ::: "memory");
        asm volatile("cp.async.wait_group 1;" ::: "memory");
        __syncthreads();

        const uint32_t base = sb + (c & 1) * STAGE;
        const uint32_t Ah = base + OFF_AH, Al = base + OFF_AL;
        const uint32_t Bt = base + OFF_B;

        #pragma unroll
        for (int s = 0; s < 4; ++s) {           // 4 x k16 steps per chunk
            uint32_t ah[4][4], al[4][4];
            #pragma unroll
            for (int i = 0; i < 4; ++i) {
                uint32_t r = m0 + i * 16 + (lane & 15);
                uint32_t off = r * APITCH + s * 32 + (lane >> 4) * 16;
                LDSM_X4(ah[i], Ah + off);
                LDSM_X4(al[i], Al + off);
            }
            uint32_t bf[4][4];
            #pragma unroll
            for (int j2 = 0; j2 < 4; ++j2) {    // 4 n16 blocks
                uint32_t n = n0w + j2 * 16 + ((lane >> 4) << 3) + (lane & 7);
                uint32_t off = n * APITCH + s * 32 + ((lane >> 3) & 1) * 16;
                LDSM_X4(bf[j2], Bt + off);
            }
            #pragma unroll
            for (int i = 0; i < 4; ++i)
                #pragma unroll
                for (int j = 0; j < 8; ++j) {   // 8 n8 tiles
                    float* d = acc[i][j];
                    uint32_t b0 = bf[j >> 1][(j & 1) * 2];
                    uint32_t b1 = bf[j >> 1][(j & 1) * 2 + 1];
                    mma_fp16(d, ah[i], b0, b1);   // ah * w
                    mma_fp16(d, al[i], b0, b1);   // al * w
                }
        }
        __syncthreads();
    }

    // ---- epilogue: acc -> smem gate staging [px][n] fp32, pitch 257 ----
    float* sg = (float*)smem;
    #pragma unroll
    for (int i = 0; i < 4; ++i)
        #pragma unroll
        for (int j = 0; j < 8; ++j) {
            int row = m0 + i * 16 + (lane >> 2);
            int col = n0w + j * 8 + (lane & 3) * 2;
            sg[row * GPITCH + col]           = acc[i][j][0];
            sg[row * GPITCH + col + 1]       = acc[i][j][1];
            sg[(row + 8) * GPITCH + col]     = acc[i][j][2];
            sg[(row + 8) * GPITCH + col + 1] = acc[i][j][3];
        }
    __syncthreads();

    // ---- fused LSTM gating, coalesced writes over px ----
    const int px = tid & 127;
    const int ch0 = tid >> 7;                 // 0/1
    #pragma unroll
    for (int t = 0; t < 32; ++t) {
        int c = t * 2 + ch0;                  // 0..63
        float gi = sg[px * GPITCH + c]        + __ldg(&bg[c]);
        float gf = sg[px * GPITCH + 64 + c]   + __ldg(&bg[64 + c]);
        float go = sg[px * GPITCH + 128 + c]  + __ldg(&bg[128 + c]);
        float gg = sg[px * GPITCH + 192 + c]  + __ldg(&bg[192 + c]);
        float ig = sigm_f(gi), fg = sigm_f(gf), og = sigm_f(go), cg = tanh_f(gg);
        size_t idx = ((size_t)(b * CH + c)) * HW + y * WW + px;
        float pc = prev_c[idx];
        float cell = ig * cg + fg * pc;
        float hid  = og * tanh_f(cell);
        out[idx] = hid;
        out[(size_t)NTOT + idx] = cell;
    }
}

// ---------------------------------------------------------------------------
extern "C" void kernel_launch(void* const* d_in, const int* in_sizes, int n_in,
                              void* d_out, int out_size)
{
    const float* x      = (const float*)d_in[0];
    const float* prev_h = (const float*)d_in[1];
    const float* prev_c = (const float*)d_in[2];
    const float* Wg     = (const float*)d_in[3];
    const float* bg     = (const float*)d_in[4];
    float* out = (float*)d_out;

    static bool attr_done = false;
    if (!attr_done) {
        cudaFuncSetAttribute(convlstm_mma_kernel,
                             cudaFuncAttributeMaxDynamicSharedMemorySize, SMEM_TOTAL);
        attr_done = true;
    }

    prep_input_kernel<<<B * HH, 256>>>(x, prev_h);
    prep_w_kernel<<<(COUT * KTOT + 255) / 256, 256>>>(Wg);
    convlstm_mma_kernel<<<B * HH, 256, SMEM_TOTAL>>>(prev_c, bg, out);
}

// round 9
// speedup vs baseline: 8.6835x; 1.3456x over previous
#include <cuda_runtime.h>
#include <cuda_fp16.h>
#include <cstdint>

// ---------------------------------------------------------------------------
// Problem constants
// ---------------------------------------------------------------------------
#define B     8
#define CIN   64
#define CH    64
#define HH    128
#define WW    128
#define CS    128              // CIN + CH
#define COUT  256              // 4 * CH
#define HW    (HH * WW)
#define KTOT  1152             // CS * 9
#define NCHUNK 18              // 9 taps x 2 channel-halves (K=64 each)
#define NTOT  (B * CH * HW)

// SMEM staging (padded pitch 144B = 72 fp16 -> conflict-free ldmatrix)
#define APITCH 144
#define A_TILE 18432           // 128 rows * 144B
#define B_TILE 36864           // 256 rows * 144B
#define OFF_A  0
#define OFF_B  A_TILE          // 18432
#define STAGE  (A_TILE + B_TILE)       // 55296
#define GPITCH 257             // fp32 gate staging pitch (odd -> conflict-free)
#define SMEM_TOTAL (128 * GPITCH * 4)  // 131584 (> 2*STAGE = 110592)

// ---------------------------------------------------------------------------
// Device scratch
// ---------------------------------------------------------------------------
__device__ __half g_inT[(size_t)B * HH * WW * CS];   // [b][y][x][ci] fp16
__device__ __half g_w[(size_t)COUT * KTOT];          // [n][k=tap*128+ci]

// ---------------------------------------------------------------------------
// Helpers (base ISA only)
// ---------------------------------------------------------------------------
__device__ __forceinline__ uint32_t smem_to_u32(const void* p) {
    uint32_t a;
    asm("{ .reg .u64 t; cvta.to.shared.u64 t, %1; cvt.u32.u64 %0, t; }"
        : "=r"(a) : "l"(p));
    return a;
}

__device__ __forceinline__ void cp16(uint32_t dst, const void* src, bool valid) {
    int sz = valid ? 16 : 0;
    asm volatile("cp.async.cg.shared.global [%0], [%1], 16, %2;"
                 :: "r"(dst), "l"(src), "r"(sz) : "memory");
}

#define LDSM_X4(r, addr) \
    asm volatile("ldmatrix.sync.aligned.m8n8.x4.shared.b16 {%0,%1,%2,%3}, [%4];" \
        : "=r"((r)[0]), "=r"((r)[1]), "=r"((r)[2]), "=r"((r)[3]) : "r"(addr))

__device__ __forceinline__ void mma_fp16(float* d, const uint32_t* a,
                                         uint32_t b0, uint32_t b1) {
    asm volatile(
        "mma.sync.aligned.m16n8k16.row.col.f32.f16.f16.f32 "
        "{%0,%1,%2,%3}, {%4,%5,%6,%7}, {%8,%9}, {%0,%1,%2,%3};"
        : "+f"(d[0]), "+f"(d[1]), "+f"(d[2]), "+f"(d[3])
        : "r"(a[0]), "r"(a[1]), "r"(a[2]), "r"(a[3]), "r"(b0), "r"(b1));
}

__device__ __forceinline__ float sigm_f(float v) { return 1.f / (1.f + __expf(-v)); }
__device__ __forceinline__ float tanh_f(float v) { return 2.f / (1.f + __expf(-2.f * v)) - 1.f; }

// ---------------------------------------------------------------------------
// Prep 1: transpose concat(x, prev_h) -> [b][y][x][ci] fp16 (half2 stores)
// ---------------------------------------------------------------------------
__global__ __launch_bounds__(256)
void prep_input_kernel(const float* __restrict__ x, const float* __restrict__ ph)
{
    __shared__ float s[64][129];
    const int bid = blockIdx.x;
    const int b = bid >> 7, y = bid & 127;
    const int tid = threadIdx.x;

    #pragma unroll
    for (int h2 = 0; h2 < 2; ++h2) {
        const int cbase = h2 * 64;
        for (int idx = tid; idx < 64 * 128; idx += 256) {
            int ci = idx >> 7, xx = idx & 127;
            int cs = cbase + ci;
            const float* src = (cs < CIN)
                ? (x  + ((size_t)b * CIN + cs) * HW)
                : (ph + ((size_t)b * CH + (cs - CIN)) * HW);
            s[ci][xx] = src[y * WW + xx];
        }
        __syncthreads();
        // 128 x * 32 ci-pairs = 4096 half2 stores, coalesced
        for (int idx = tid; idx < 128 * 32; idx += 256) {
            int xx = idx >> 5, cp = (idx & 31) * 2;
            __half2 v = __floats2half2_rn(s[cp][xx], s[cp + 1][xx]);
            size_t o = ((size_t)(b * HH + y) * WW + xx) * CS + cbase + cp;
            *reinterpret_cast<__half2*>(g_inT + o) = v;
        }
        __syncthreads();
    }
}

// ---------------------------------------------------------------------------
// Prep 2: weights [oc][cs][ky][kx] -> [n][k = tap*128 + cs], fp16
// ---------------------------------------------------------------------------
__global__ __launch_bounds__(256)
void prep_w_kernel(const float* __restrict__ Wg)
{
    int idx = blockIdx.x * blockDim.x + threadIdx.x;
    if (idx >= COUT * KTOT) return;
    int n = idx / KTOT, k = idx - n * KTOT;
    int tap = k >> 7, cs = k & 127;
    g_w[idx] = __float2half_rn(Wg[(size_t)n * KTOT + cs * 9 + tap]);
}

// ---------------------------------------------------------------------------
// Main: implicit-GEMM conv (single-pass fp16) + fused LSTM gating.
// One CTA = one image row: M=128, N=256, K=1152 (18 chunks of 64).
// 256 threads = 8 warps in 2(M) x 4(N) grid; warp tile 64x64.
// ---------------------------------------------------------------------------
__device__ __forceinline__ void issue_chunk(int chunk, uint32_t base,
                                            int b, int y, int tid)
{
    const int tap = chunk >> 1;
    const int ci0 = (chunk & 1) * 64;
    const int dy = tap / 3 - 1, dxx = tap % 3 - 1;
    const int yy = y + dy;
    const bool yok = (unsigned)yy < (unsigned)HH;
    const int yc = yok ? yy : 0;

    // A: 128 rows x 8 segs = 1024 cp.async -> 4/thread
    #pragma unroll
    for (int q = 0; q < 4; ++q) {
        int idx = q * 256 + tid;
        int row = idx >> 3, seg = idx & 7;
        int xr = row + dxx;
        bool valid = yok && ((unsigned)xr < (unsigned)WW);
        int xc = ((unsigned)xr < (unsigned)WW) ? xr : 0;
        const void* src = g_inT + (((size_t)(b * HH + yc) * WW + xc) * CS
                                   + ci0 + seg * 8);
        uint32_t dst = base + OFF_A + row * APITCH + seg * 16;
        cp16(dst, src, valid);
    }
    // B: 256 rows x 8 segs = 2048 -> 8/thread
    #pragma unroll
    for (int q = 0; q < 8; ++q) {
        int idx = q * 256 + tid;
        int n = idx >> 3, seg = idx & 7;
        const void* src = g_w + ((size_t)n * KTOT + tap * 128 + ci0 + seg * 8);
        uint32_t dst = base + OFF_B + n * APITCH + seg * 16;
        cp16(dst, src, true);
    }
}

__global__ __launch_bounds__(256)
void convlstm_mma_kernel(const float* __restrict__ prev_c,
                         const float* __restrict__ bg,
                         float* __restrict__ out)
{
    extern __shared__ char smem[];
    const uint32_t sb = smem_to_u32(smem);
    const int tid = threadIdx.x, wid = tid >> 5, lane = tid & 31;
    const int bid = blockIdx.x;
    const int b = bid >> 7, y = bid & 127;
    const int m0 = (wid & 1) * 64;        // warp m origin (2 m-warps)
    const int n0w = (wid >> 1) * 64;      // warp n origin (4 n-warps)

    float acc[4][8][4];
    #pragma unroll
    for (int i = 0; i < 4; ++i)
        #pragma unroll
        for (int j = 0; j < 8; ++j)
            #pragma unroll
            for (int t = 0; t < 4; ++t) acc[i][j][t] = 0.f;

    issue_chunk(0, sb, b, y, tid);
    asm volatile("cp.async.commit_group;" ::: "memory");

    for (int c = 0; c < NCHUNK; ++c) {
        if (c + 1 < NCHUNK)
            issue_chunk(c + 1, sb + ((c + 1) & 1) * STAGE, b, y, tid);
        asm volatile("cp.async.commit_group;" ::: "memory");
        asm volatile("cp.async.wait_group 1;" ::: "memory");
        __syncthreads();

        const uint32_t base = sb + (c & 1) * STAGE;
        const uint32_t At = base + OFF_A;
        const uint32_t Bt = base + OFF_B;

        #pragma unroll
        for (int s = 0; s < 4; ++s) {           // 4 x k16 steps per chunk
            uint32_t af[4][4];
            #pragma unroll
            for (int i = 0; i < 4; ++i) {
                uint32_t r = m0 + i * 16 + (lane & 15);
                uint32_t off = r * APITCH + s * 32 + (lane >> 4) * 16;
                LDSM_X4(af[i], At + off);
            }
            uint32_t bf[4][4];
            #pragma unroll
            for (int j2 = 0; j2 < 4; ++j2) {    // 4 n16 blocks
                uint32_t n = n0w + j2 * 16 + ((lane >> 4) << 3) + (lane & 7);
                uint32_t off = n * APITCH + s * 32 + ((lane >> 3) & 1) * 16;
                LDSM_X4(bf[j2], Bt + off);
            }
            #pragma unroll
            for (int i = 0; i < 4; ++i)
                #pragma unroll
                for (int j = 0; j < 8; ++j) {   // 8 n8 tiles
                    uint32_t b0 = bf[j >> 1][(j & 1) * 2];
                    uint32_t b1 = bf[j >> 1][(j & 1) * 2 + 1];
                    mma_fp16(acc[i][j], af[i], b0, b1);
                }
        }
        __syncthreads();
    }

    // ---- epilogue: acc -> smem gate staging [px][n] fp32, pitch 257 ----
    float* sg = (float*)smem;
    #pragma unroll
    for (int i = 0; i < 4; ++i)
        #pragma unroll
        for (int j = 0; j < 8; ++j) {
            int row = m0 + i * 16 + (lane >> 2);
            int col = n0w + j * 8 + (lane & 3) * 2;
            sg[row * GPITCH + col]           = acc[i][j][0];
            sg[row * GPITCH + col + 1]       = acc[i][j][1];
            sg[(row + 8) * GPITCH + col]     = acc[i][j][2];
            sg[(row + 8) * GPITCH + col + 1] = acc[i][j][3];
        }
    __syncthreads();

    // ---- fused LSTM gating, coalesced writes over px ----
    const int px = tid & 127;
    const int ch0 = tid >> 7;                 // 0/1
    #pragma unroll
    for (int t = 0; t < 32; ++t) {
        int c = t * 2 + ch0;                  // 0..63
        float gi = sg[px * GPITCH + c]        + __ldg(&bg[c]);
        float gf = sg[px * GPITCH + 64 + c]   + __ldg(&bg[64 + c]);
        float go = sg[px * GPITCH + 128 + c]  + __ldg(&bg[128 + c]);
        float gg = sg[px * GPITCH + 192 + c]  + __ldg(&bg[192 + c]);
        float ig = sigm_f(gi), fg = sigm_f(gf), og = sigm_f(go), cg = tanh_f(gg);
        size_t idx = ((size_t)(b * CH + c)) * HW + y * WW + px;
        float pc = prev_c[idx];
        float cell = ig * cg + fg * pc;
        float hid  = og * tanh_f(cell);
        out[idx] = hid;
        out[(size_t)NTOT + idx] = cell;
    }
}

// ---------------------------------------------------------------------------
extern "C" void kernel_launch(void* const* d_in, const int* in_sizes, int n_in,
                              void* d_out, int out_size)
{
    const float* x      = (const float*)d_in[0];
    const float* prev_h = (const float*)d_in[1];
    const float* prev_c = (const float*)d_in[2];
    const float* Wg     = (const float*)d_in[3];
    const float* bg     = (const float*)d_in[4];
    float* out = (float*)d_out;

    static bool attr_done = false;
    if (!attr_done) {
        cudaFuncSetAttribute(convlstm_mma_kernel,
                             cudaFuncAttributeMaxDynamicSharedMemorySize, SMEM_TOTAL);
        attr_done = true;
    }

    prep_input_kernel<<<B * HH, 256>>>(x, prev_h);
    prep_w_kernel<<<(COUT * KTOT + 255) / 256, 256>>>(Wg);
    convlstm_mma_kernel<<<B * HH, 256, SMEM_TOTAL>>>(prev_c, bg, out);
}

// round 11
// speedup vs baseline: 9.1384x; 1.0524x over previous
#include <cuda_runtime.h>
#include <cuda_fp16.h>
#include <cstdint>

// ---------------------------------------------------------------------------
// Problem constants
// ---------------------------------------------------------------------------
#define B     8
#define CIN   64
#define CH    64
#define HH    128
#define WW    128
#define CS    128              // CIN + CH
#define COUT  256              // 4 * CH
#define HW    (HH * WW)
#define KTOT  1152             // CS * 9
#define NCHUNK 18              // 2 halves x 9 taps (K=64 each)
#define NTOT  (B * CH * HW)

// SMEM layout (pitch 144B = 9 x 16B banks -> conflict-free ldmatrix)
#define PITCH  144
#define AROW   (130 * PITCH)          // 18720 B: one input row, 130 px x 64ch
#define A_HALF (3 * AROW)             // 56160 B: rows y-1, y, y+1
#define A_TOT  (2 * A_HALF)           // 112320 B: double-buffered per ci-half
#define B_TILE (256 * PITCH)          // 36864 B
#define NBSTG  3
#define OFF_B  A_TOT                  // B stages start here
#define SMEM_TOTAL (A_TOT + NBSTG * B_TILE)   // 222912 B
#define GPITCH 257                    // fp32 gate staging pitch (aliases base)

// ---------------------------------------------------------------------------
// Device scratch
// ---------------------------------------------------------------------------
__device__ __half g_inT[(size_t)B * HH * WW * CS];   // [b][y][x][ci] fp16
__device__ __half g_w[(size_t)COUT * KTOT];          // [n][k=tap*128+ci]

// ---------------------------------------------------------------------------
// Helpers (base ISA only)
// ---------------------------------------------------------------------------
__device__ __forceinline__ uint32_t smem_to_u32(const void* p) {
    uint32_t a;
    asm("{ .reg .u64 t; cvta.to.shared.u64 t, %1; cvt.u32.u64 %0, t; }"
        : "=r"(a) : "l"(p));
    return a;
}

__device__ __forceinline__ void cp16(uint32_t dst, const void* src, bool valid) {
    int sz = valid ? 16 : 0;
    asm volatile("cp.async.cg.shared.global [%0], [%1], 16, %2;"
                 :: "r"(dst), "l"(src), "r"(sz) : "memory");
}

#define CP_COMMIT() asm volatile("cp.async.commit_group;" ::: "memory")
#define CP_WAIT2()  asm volatile("cp.async.wait_group 2;" ::: "memory")

#define LDSM_X4(r, addr) \
    asm volatile("ldmatrix.sync.aligned.m8n8.x4.shared.b16 {%0,%1,%2,%3}, [%4];" \
        : "=r"((r)[0]), "=r"((r)[1]), "=r"((r)[2]), "=r"((r)[3]) : "r"(addr))

__device__ __forceinline__ void mma_fp16(float* d, const uint32_t* a,
                                         uint32_t b0, uint32_t b1) {
    asm volatile(
        "mma.sync.aligned.m16n8k16.row.col.f32.f16.f16.f32 "
        "{%0,%1,%2,%3}, {%4,%5,%6,%7}, {%8,%9}, {%0,%1,%2,%3};"
        : "+f"(d[0]), "+f"(d[1]), "+f"(d[2]), "+f"(d[3])
        : "r"(a[0]), "r"(a[1]), "r"(a[2]), "r"(a[3]), "r"(b0), "r"(b1));
}

__device__ __forceinline__ float sigm_f(float v) { return 1.f / (1.f + __expf(-v)); }
__device__ __forceinline__ float tanh_f(float v) { return 2.f / (1.f + __expf(-2.f * v)) - 1.f; }

// ---------------------------------------------------------------------------
// Prep 1: transpose concat(x, prev_h) -> [b][y][x][ci] fp16 (float4 loads)
// ---------------------------------------------------------------------------
__global__ __launch_bounds__(256)
void prep_input_kernel(const float* __restrict__ x, const float* __restrict__ ph)
{
    __shared__ float s[64][129];
    const int bid = blockIdx.x;
    const int b = bid >> 7, y = bid & 127;
    const int tid = threadIdx.x;

    #pragma unroll
    for (int h2 = 0; h2 < 2; ++h2) {
        const int cbase = h2 * 64;
        // 64 ch x 32 float4 = 2048 vector loads -> 8/thread
        for (int idx = tid; idx < 64 * 32; idx += 256) {
            int ci = idx >> 5, x4 = (idx & 31) * 4;
            int cs = cbase + ci;
            const float* src = (cs < CIN)
                ? (x  + ((size_t)b * CIN + cs) * HW)
                : (ph + ((size_t)b * CH + (cs - CIN)) * HW);
            float4 v = *reinterpret_cast<const float4*>(src + y * WW + x4);
            s[ci][x4]     = v.x;
            s[ci][x4 + 1] = v.y;
            s[ci][x4 + 2] = v.z;
            s[ci][x4 + 3] = v.w;
        }
        __syncthreads();
        // 128 x * 32 ci-pairs = 4096 half2 stores, coalesced
        for (int idx = tid; idx < 128 * 32; idx += 256) {
            int xx = idx >> 5, cp = (idx & 31) * 2;
            __half2 v = __floats2half2_rn(s[cp][xx], s[cp + 1][xx]);
            size_t o = ((size_t)(b * HH + y) * WW + xx) * CS + cbase + cp;
            *reinterpret_cast<__half2*>(g_inT + o) = v;
        }
        __syncthreads();
    }
}

// ---------------------------------------------------------------------------
// Prep 2: weights [oc][cs][ky][kx] -> [n][k = tap*128 + cs], fp16
// ---------------------------------------------------------------------------
__global__ __launch_bounds__(256)
void prep_w_kernel(const float* __restrict__ Wg)
{
    int idx = blockIdx.x * blockDim.x + threadIdx.x;
    if (idx >= COUT * KTOT) return;
    int n = idx / KTOT, k = idx - n * KTOT;
    int tap = k >> 7, cs = k & 127;
    g_w[idx] = __float2half_rn(Wg[(size_t)n * KTOT + cs * 9 + tap]);
}

// ---------------------------------------------------------------------------
// Main: implicit-GEMM conv (fp16) + fused LSTM gating.
// One CTA = one image row: M=128, N=256, K=1152.
// A: 3 full input rows staged once per ci-half (halo baked in, zero-filled).
// B: 3-stage cp.async pipeline over 18 chunks (half-major, tap-minor).
// 256 threads = 8 warps, warp tile 64(M) x 64(N).
// ---------------------------------------------------------------------------
__device__ __forceinline__ void issue_A_half(int half, uint32_t sb,
                                             int b, int y, int tid)
{
    const int ci0 = half * 64;
    const uint32_t abase = sb + half * A_HALF;
    // 3 rows x 130 px x 8 segs = 3120 cp.async
    #pragma unroll
    for (int q = 0; q < 13; ++q) {
        int idx = q * 256 + tid;
        if (idx < 3120) {
            int r = idx / 1040;              // row 0..2 (yy = y + r - 1)
            int rem = idx - r * 1040;
            int pxi = rem >> 3, seg = rem & 7;   // pxi 0..129 -> px = pxi-1
            int yy = y + r - 1;
            int px = pxi - 1;
            bool valid = ((unsigned)yy < (unsigned)HH) &
                         ((unsigned)px < (unsigned)WW);
            int yc = ((unsigned)yy < (unsigned)HH) ? yy : 0;
            int xc = ((unsigned)px < (unsigned)WW) ? px : 0;
            const void* src = g_inT + (((size_t)(b * HH + yc) * WW + xc) * CS
                                       + ci0 + seg * 8);
            uint32_t dst = abase + r * AROW + pxi * PITCH + seg * 16;
            cp16(dst, src, valid);
        }
    }
}

__device__ __forceinline__ void issue_B(int chunk, uint32_t sb, int tid)
{
    const int half = chunk / 9, tap = chunk - half * 9;
    const uint32_t bbase = sb + OFF_B + (chunk % NBSTG) * B_TILE;
    // 256 rows x 8 segs = 2048 -> 8/thread
    #pragma unroll
    for (int q = 0; q < 8; ++q) {
        int idx = q * 256 + tid;
        int n = idx >> 3, seg = idx & 7;
        const void* src = g_w + ((size_t)n * KTOT + tap * 128 + half * 64
                                 + seg * 8);
        uint32_t dst = bbase + n * PITCH + seg * 16;
        cp16(dst, src, true);
    }
}

__global__ __launch_bounds__(256)
void convlstm_mma_kernel(const float* __restrict__ prev_c,
                         const float* __restrict__ bg,
                         float* __restrict__ out)
{
    extern __shared__ char smem[];
    const uint32_t sb = smem_to_u32(smem);
    const int tid = threadIdx.x, wid = tid >> 5, lane = tid & 31;
    const int bid = blockIdx.x;
    const int b = bid >> 7, y = bid & 127;
    const int m0 = (wid & 1) * 64;        // warp m origin (2 m-warps)
    const int n0w = (wid >> 1) * 64;      // warp n origin (4 n-warps)

    float acc[4][8][4];
    #pragma unroll
    for (int i = 0; i < 4; ++i)
        #pragma unroll
        for (int j = 0; j < 8; ++j)
            #pragma unroll
            for (int t = 0; t < 4; ++t) acc[i][j][t] = 0.f;

    // Prologue: commit#1 = {A0, B0}, commit#2 = {A1, B1}
    issue_A_half(0, sb, b, y, tid);
    issue_B(0, sb, tid);
    CP_COMMIT();
    issue_A_half(1, sb, b, y, tid);
    issue_B(1, sb, tid);
    CP_COMMIT();

    for (int c = 0; c < NCHUNK; ++c) {
        if (c + 2 < NCHUNK) issue_B(c + 2, sb, tid);
        CP_COMMIT();               // commit #(c+3)
        CP_WAIT2();                // -> commit #(c+1) done -> B(c) (+A) ready
        __syncthreads();

        const int half = c / 9, tap = c - half * 9;
        const int ky = tap / 3, kx = tap - ky * 3;
        const uint32_t Arow = sb + half * A_HALF + ky * AROW;
        const uint32_t Bt = sb + OFF_B + (c % NBSTG) * B_TILE;

        #pragma unroll
        for (int s = 0; s < 4; ++s) {           // 4 x k16 steps per chunk
            uint32_t af[4][4];
            #pragma unroll
            for (int i = 0; i < 4; ++i) {
                // staged px index = actual px + 1; actual = m + kx - 1
                uint32_t r = m0 + i * 16 + (lane & 15) + kx;
                uint32_t off = r * PITCH + s * 32 + (lane >> 4) * 16;
                LDSM_X4(af[i], Arow + off);
            }
            uint32_t bf[4][4];
            #pragma unroll
            for (int j2 = 0; j2 < 4; ++j2) {    // 4 n16 blocks
                uint32_t n = n0w + j2 * 16 + ((lane >> 4) << 3) + (lane & 7);
                uint32_t off = n * PITCH + s * 32 + ((lane >> 3) & 1) * 16;
                LDSM_X4(bf[j2], Bt + off);
            }
            #pragma unroll
            for (int i = 0; i < 4; ++i)
                #pragma unroll
                for (int j = 0; j < 8; ++j) {   // 8 n8 tiles
                    uint32_t b0 = bf[j >> 1][(j & 1) * 2];
                    uint32_t b1 = bf[j >> 1][(j & 1) * 2 + 1];
                    mma_fp16(acc[i][j], af[i], b0, b1);
                }
        }
        __syncthreads();
    }

    // ---- epilogue: acc -> smem gate staging [px][n] fp32, pitch 257 ----
    float* sg = (float*)smem;
    #pragma unroll
    for (int i = 0; i < 4; ++i)
        #pragma unroll
        for (int j = 0; j < 8; ++j) {
            int row = m0 + i * 16 + (lane >> 2);
            int col = n0w + j * 8 + (lane & 3) * 2;
            sg[row * GPITCH + col]           = acc[i][j][0];
            sg[row * GPITCH + col + 1]       = acc[i][j][1];
            sg[(row + 8) * GPITCH + col]     = acc[i][j][2];
            sg[(row + 8) * GPITCH + col + 1] = acc[i][j][3];
        }
    __syncthreads();

    // ---- fused LSTM gating, coalesced writes over px ----
    const int px = tid & 127;
    const int ch0 = tid >> 7;                 // 0/1
    #pragma unroll
    for (int t = 0; t < 32; ++t) {
        int c = t * 2 + ch0;                  // 0..63
        float gi = sg[px * GPITCH + c]        + __ldg(&bg[c]);
        float gf = sg[px * GPITCH + 64 + c]   + __ldg(&bg[64 + c]);
        float go = sg[px * GPITCH + 128 + c]  + __ldg(&bg[128 + c]);
        float gg = sg[px * GPITCH + 192 + c]  + __ldg(&bg[192 + c]);
        float ig = sigm_f(gi), fg = sigm_f(gf), og = sigm_f(go), cg = tanh_f(gg);
        size_t idx = ((size_t)(b * CH + c)) * HW + y * WW + px;
        float pc = prev_c[idx];
        float cell = ig * cg + fg * pc;
        float hid  = og * tanh_f(cell);
        out[idx] = hid;
        out[(size_t)NTOT + idx] = cell;
    }
}

// ---------------------------------------------------------------------------
extern "C" void kernel_launch(void* const* d_in, const int* in_sizes, int n_in,
                              void* d_out, int out_size)
{
    const float* x      = (const float*)d_in[0];
    const float* prev_h = (const float*)d_in[1];
    const float* prev_c = (const float*)d_in[2];
    const float* Wg     = (const float*)d_in[3];
    const float* bg     = (const float*)d_in[4];
    float* out = (float*)d_out;

    static bool attr_done = false;
    if (!attr_done) {
        cudaFuncSetAttribute(convlstm_mma_kernel,
                             cudaFuncAttributeMaxDynamicSharedMemorySize, SMEM_TOTAL);
        attr_done = true;
    }

    prep_input_kernel<<<B * HH, 256>>>(x, prev_h);
    prep_w_kernel<<<(COUT * KTOT + 255) / 256, 256>>>(Wg);
    convlstm_mma_kernel<<<B * HH, 256, SMEM_TOTAL>>>(prev_c, bg, out);
}

// round 13
// speedup vs baseline: 11.2135x; 1.2271x over previous
#include <cuda_runtime.h>
#include <cuda_fp16.h>
#include <cstdint>

// ---------------------------------------------------------------------------
// Problem constants
// ---------------------------------------------------------------------------
#define B     8
#define CIN   64
#define CH    64
#define HH    128
#define WW    128
#define CS    128              // CIN + CH
#define COUT  256              // 4 * CH
#define HW    (HH * WW)
#define KTOT  1152             // CS * 9
#define NCHUNK 18              // 2 halves x 9 taps (K=64 each)
#define NTOT  (B * CH * HW)

// CTA tile: M=64 px, N=128 gate-rows (all 4 gates x 32 channels)
#define MT    64
#define NT    128

// SMEM layout (pitch 144B = 9 x 16B banks -> conflict-free ldmatrix)
#define PITCH  144
#define AROW   (66 * PITCH)           //  9504 B: one input row, 66 px x 64ch
#define A_HALF (3 * AROW)             // 28512 B: rows y-1, y, y+1
#define A_TOT  (2 * A_HALF)           // 57024 B: double-buffered per ci-half
#define B_TILE (NT * PITCH)           // 18432 B
#define NBSTG  3
#define OFF_B  A_TOT
#define SMEM_TOTAL (A_TOT + NBSTG * B_TILE)   // 112320 B -> 2 CTAs/SM
#define GPITCH 129                    // fp32 gate staging pitch (aliases base)

// ---------------------------------------------------------------------------
// Device scratch
// ---------------------------------------------------------------------------
__device__ __half g_inT[(size_t)B * HH * WW * CS];   // [b][y][x][ci] fp16
__device__ __half g_w[(size_t)COUT * KTOT];          // [n][k], n gate-interleaved

// ---------------------------------------------------------------------------
// Helpers (base ISA only)
// ---------------------------------------------------------------------------
__device__ __forceinline__ uint32_t smem_to_u32(const void* p) {
    uint32_t a;
    asm("{ .reg .u64 t; cvta.to.shared.u64 t, %1; cvt.u32.u64 %0, t; }"
        : "=r"(a) : "l"(p));
    return a;
}

__device__ __forceinline__ void cp16(uint32_t dst, const void* src, bool valid) {
    int sz = valid ? 16 : 0;
    asm volatile("cp.async.cg.shared.global [%0], [%1], 16, %2;"
                 :: "r"(dst), "l"(src), "r"(sz) : "memory");
}

#define CP_COMMIT() asm volatile("cp.async.commit_group;" ::: "memory")
#define CP_WAIT2()  asm volatile("cp.async.wait_group 2;" ::: "memory")

#define LDSM_X4(r, addr) \
    asm volatile("ldmatrix.sync.aligned.m8n8.x4.shared.b16 {%0,%1,%2,%3}, [%4];" \
        : "=r"((r)[0]), "=r"((r)[1]), "=r"((r)[2]), "=r"((r)[3]) : "r"(addr))

__device__ __forceinline__ void mma_fp16(float* d, const uint32_t* a,
                                         uint32_t b0, uint32_t b1) {
    asm volatile(
        "mma.sync.aligned.m16n8k16.row.col.f32.f16.f16.f32 "
        "{%0,%1,%2,%3}, {%4,%5,%6,%7}, {%8,%9}, {%0,%1,%2,%3};"
        : "+f"(d[0]), "+f"(d[1]), "+f"(d[2]), "+f"(d[3])
        : "r"(a[0]), "r"(a[1]), "r"(a[2]), "r"(a[3]), "r"(b0), "r"(b1));
}

__device__ __forceinline__ float sigm_f(float v) { return 1.f / (1.f + __expf(-v)); }
__device__ __forceinline__ float tanh_f(float v) { return 2.f / (1.f + __expf(-2.f * v)) - 1.f; }

// ---------------------------------------------------------------------------
// Prep 1: transpose concat(x, prev_h) -> [b][y][x][ci] fp16 (float4 loads)
// ---------------------------------------------------------------------------
__global__ __launch_bounds__(256)
void prep_input_kernel(const float* __restrict__ x, const float* __restrict__ ph)
{
    __shared__ float s[64][129];
    const int bid = blockIdx.x;
    const int b = bid >> 7, y = bid & 127;
    const int tid = threadIdx.x;

    #pragma unroll
    for (int h2 = 0; h2 < 2; ++h2) {
        const int cbase = h2 * 64;
        for (int idx = tid; idx < 64 * 32; idx += 256) {
            int ci = idx >> 5, x4 = (idx & 31) * 4;
            int cs = cbase + ci;
            const float* src = (cs < CIN)
                ? (x  + ((size_t)b * CIN + cs) * HW)
                : (ph + ((size_t)b * CH + (cs - CIN)) * HW);
            float4 v = *reinterpret_cast<const float4*>(src + y * WW + x4);
            s[ci][x4]     = v.x;
            s[ci][x4 + 1] = v.y;
            s[ci][x4 + 2] = v.z;
            s[ci][x4 + 3] = v.w;
        }
        __syncthreads();
        for (int idx = tid; idx < 128 * 32; idx += 256) {
            int xx = idx >> 5, cp = (idx & 31) * 2;
            __half2 v = __floats2half2_rn(s[cp][xx], s[cp + 1][xx]);
            size_t o = ((size_t)(b * HH + y) * WW + xx) * CS + cbase + cp;
            *reinterpret_cast<__half2*>(g_inT + o) = v;
        }
        __syncthreads();
    }
}

// ---------------------------------------------------------------------------
// Prep 2: weights -> [n][k=tap*128+cs], fp16, gate-interleaved N order:
//   n = (c>>5)*128 + gate*32 + (c&31)   (oc = gate*64 + c)
// so each N-half (128 rows) holds all 4 gates for 32 channels.
// ---------------------------------------------------------------------------
__global__ __launch_bounds__(256)
void prep_w_kernel(const float* __restrict__ Wg)
{
    int idx = blockIdx.x * blockDim.x + threadIdx.x;
    if (idx >= COUT * KTOT) return;
    int n = idx / KTOT, k = idx - n * KTOT;
    int tap = k >> 7, cs = k & 127;
    int chblk = n >> 7, gate = (n >> 5) & 3, cl = n & 31;
    int oc = gate * 64 + chblk * 32 + cl;
    g_w[idx] = __float2half_rn(Wg[(size_t)oc * KTOT + cs * 9 + tap]);
}

// ---------------------------------------------------------------------------
// Main: implicit-GEMM conv (fp16) + fused LSTM gating.
// CTA tile M=64 px x N=128 gate-rows, K=1152; 2 CTAs/SM.
// 256 threads = 8 warps in 2(M) x 4(N); warp tile 32x32.
// ---------------------------------------------------------------------------
__device__ __forceinline__ void issue_A_half(int half, uint32_t sb,
                                             int b, int y, int mx0, int tid)
{
    const int ci0 = half * 64;
    const uint32_t abase = sb + half * A_HALF;
    // 3 rows x 66 px x 8 segs = 1584 cp.async
    #pragma unroll
    for (int q = 0; q < 7; ++q) {
        int idx = q * 256 + tid;
        if (idx < 1584) {
            int r = idx / 528;                   // row 0..2
            int rem = idx - r * 528;
            int pxi = rem >> 3, seg = rem & 7;   // pxi 0..65
            int yy = y + r - 1;
            int px = mx0 + pxi - 1;
            bool valid = ((unsigned)yy < (unsigned)HH) &
                         ((unsigned)px < (unsigned)WW);
            int yc = ((unsigned)yy < (unsigned)HH) ? yy : 0;
            int xc = ((unsigned)px < (unsigned)WW) ? px : 0;
            const void* src = g_inT + (((size_t)(b * HH + yc) * WW + xc) * CS
                                       + ci0 + seg * 8);
            uint32_t dst = abase + r * AROW + pxi * PITCH + seg * 16;
            cp16(dst, src, valid);
        }
    }
}

__device__ __forceinline__ void issue_B(int chunk, uint32_t sb, int n0, int tid)
{
    const int half = chunk / 9, tap = chunk - half * 9;
    const uint32_t bbase = sb + OFF_B + (chunk % NBSTG) * B_TILE;
    // 128 rows x 8 segs = 1024 -> 4/thread
    #pragma unroll
    for (int q = 0; q < 4; ++q) {
        int idx = q * 256 + tid;
        int n = idx >> 3, seg = idx & 7;
        const void* src = g_w + ((size_t)(n0 + n) * KTOT + tap * 128 + half * 64
                                 + seg * 8);
        uint32_t dst = bbase + n * PITCH + seg * 16;
        cp16(dst, src, true);
    }
}

__global__ __launch_bounds__(256, 2)
void convlstm_mma_kernel(const float* __restrict__ prev_c,
                         const float* __restrict__ bg,
                         float* __restrict__ out)
{
    extern __shared__ char smem[];
    const uint32_t sb = smem_to_u32(smem);
    const int tid = threadIdx.x, wid = tid >> 5, lane = tid & 31;
    const int bid = blockIdx.x;
    const int mhalf = bid & 1, nhalf = (bid >> 1) & 1;
    const int y = (bid >> 2) & 127, b = bid >> 9;
    const int mx0 = mhalf * MT;           // pixel-tile origin
    const int nb0 = nhalf * NT;           // weight-row origin
    const int m0 = (wid & 1) * 32;        // warp m origin (2 m-warps)
    const int n0w = (wid >> 1) * 32;      // warp n origin (4 n-warps)

    float acc[2][4][4];
    #pragma unroll
    for (int i = 0; i < 2; ++i)
        #pragma unroll
        for (int j = 0; j < 4; ++j)
            #pragma unroll
            for (int t = 0; t < 4; ++t) acc[i][j][t] = 0.f;

    // Prologue: commit#1 = {A0, B0}, commit#2 = {A1, B1}
    issue_A_half(0, sb, b, y, mx0, tid);
    issue_B(0, sb, nb0, tid);
    CP_COMMIT();
    issue_A_half(1, sb, b, y, mx0, tid);
    issue_B(1, sb, nb0, tid);
    CP_COMMIT();

    for (int c = 0; c < NCHUNK; ++c) {
        if (c + 2 < NCHUNK) issue_B(c + 2, sb, nb0, tid);
        CP_COMMIT();
        CP_WAIT2();                // B(c) (+A both halves) ready
        __syncthreads();

        const int half = c / 9, tap = c - half * 9;
        const int ky = tap / 3, kx = tap - ky * 3;
        const uint32_t Arow = sb + half * A_HALF + ky * AROW;
        const uint32_t Bt = sb + OFF_B + (c % NBSTG) * B_TILE;

        #pragma unroll
        for (int s = 0; s < 4; ++s) {           // 4 x k16 steps per chunk
            uint32_t af[2][4];
            #pragma unroll
            for (int i = 0; i < 2; ++i) {
                // staged px index = local px + 1; read px = m + kx - 1
                uint32_t r = m0 + i * 16 + (lane & 15) + kx;
                uint32_t off = r * PITCH + s * 32 + (lane >> 4) * 16;
                LDSM_X4(af[i], Arow + off);
            }
            uint32_t bf[2][4];
            #pragma unroll
            for (int j2 = 0; j2 < 2; ++j2) {    // 2 n16 blocks
                uint32_t n = n0w + j2 * 16 + ((lane >> 4) << 3) + (lane & 7);
                uint32_t off = n * PITCH + s * 32 + ((lane >> 3) & 1) * 16;
                LDSM_X4(bf[j2], Bt + off);
            }
            #pragma unroll
            for (int i = 0; i < 2; ++i)
                #pragma unroll
                for (int j = 0; j < 4; ++j) {   // 4 n8 tiles
                    uint32_t b0 = bf[j >> 1][(j & 1) * 2];
                    uint32_t b1 = bf[j >> 1][(j & 1) * 2 + 1];
                    mma_fp16(acc[i][j], af[i], b0, b1);
                }
        }
        __syncthreads();
    }

    // ---- epilogue: acc -> smem gate staging [px][n] fp32, pitch 129 ----
    float* sg = (float*)smem;
    #pragma unroll
    for (int i = 0; i < 2; ++i)
        #pragma unroll
        for (int j = 0; j < 4; ++j) {
            int row = m0 + i * 16 + (lane >> 2);
            int col = n0w + j * 8 + (lane & 3) * 2;
            sg[row * GPITCH + col]           = acc[i][j][0];
            sg[row * GPITCH + col + 1]       = acc[i][j][1];
            sg[(row + 8) * GPITCH + col]     = acc[i][j][2];
            sg[(row + 8) * GPITCH + col + 1] = acc[i][j][3];
        }
    __syncthreads();

    // ---- fused LSTM gating: 64 px x 32 channels, all 4 gates local ----
    const int px = tid & 63;
    const int grp = tid >> 6;                 // 0..3
    #pragma unroll
    for (int t = 0; t < 8; ++t) {
        int cl = grp * 8 + t;                 // 0..31
        float gi = sg[px * GPITCH + cl]       + __ldg(&bg[nhalf * 32 + cl]);
        float gf = sg[px * GPITCH + 32 + cl]  + __ldg(&bg[64 + nhalf * 32 + cl]);
        float go = sg[px * GPITCH + 64 + cl]  + __ldg(&bg[128 + nhalf * 32 + cl]);
        float gg = sg[px * GPITCH + 96 + cl]  + __ldg(&bg[192 + nhalf * 32 + cl]);
        float ig = sigm_f(gi), fg = sigm_f(gf), og = sigm_f(go), cg = tanh_f(gg);
        int cgl = nhalf * 32 + cl;
        size_t idx = ((size_t)(b * CH + cgl)) * HW + y * WW + mx0 + px;
        float pc = prev_c[idx];
        float cell = ig * cg + fg * pc;
        float hid  = og * tanh_f(cell);
        out[idx] = hid;
        out[(size_t)NTOT + idx] = cell;
    }
}

// ---------------------------------------------------------------------------
extern "C" void kernel_launch(void* const* d_in, const int* in_sizes, int n_in,
                              void* d_out, int out_size)
{
    const float* x      = (const float*)d_in[0];
    const float* prev_h = (const float*)d_in[1];
    const float* prev_c = (const float*)d_in[2];
    const float* Wg     = (const float*)d_in[3];
    const float* bg     = (const float*)d_in[4];
    float* out = (float*)d_out;

    static bool attr_done = false;
    if (!attr_done) {
        cudaFuncSetAttribute(convlstm_mma_kernel,
                             cudaFuncAttributeMaxDynamicSharedMemorySize, SMEM_TOTAL);
        attr_done = true;
    }

    prep_input_kernel<<<B * HH, 256>>>(x, prev_h);
    prep_w_kernel<<<(COUT * KTOT + 255) / 256, 256>>>(Wg);
    convlstm_mma_kernel<<<B * HH * 4, 256, SMEM_TOTAL>>>(prev_c, bg, out);
}